// round 9
// baseline (speedup 1.0000x reference)
#include <cuda_runtime.h>
#include <cuda_fp16.h>

typedef unsigned int u32;

#define NCONV 8
#define HO 62
#define WO 62
#define PX 48      // bytes per feature pixel (32 data + 16 pad -> conflict-free ldmatrix)

// precomputed folded B-matrix: [tap][n][k] fp16
// k=0: bw_hi | k=1..8: scaled spline | k=9: bw_hi | k=10: bw_lo | k>=11: 0
__device__ __half g_Bt[9 * 8 * 16];

__device__ __forceinline__ u32 smem_u32(const void* p) {
    u32 a;
    asm("{ .reg .u64 t; cvta.to.shared.u64 t, %1; cvt.u32.u64 %0, t; }" : "=r"(a) : "l"(p));
    return a;
}
__device__ __forceinline__ u32 pack_h2(float lo, float hi) {
    u32 r; asm("cvt.rn.f16x2.f32 %0, %1, %2;" : "=r"(r) : "f"(hi), "f"(lo)); return r;
}
__device__ __forceinline__ void ldsm_x4(u32 &r0, u32 &r1, u32 &r2, u32 &r3, u32 addr) {
    asm volatile("ldmatrix.sync.aligned.m8n8.x4.shared.b16 {%0,%1,%2,%3}, [%4];"
                 : "=r"(r0), "=r"(r1), "=r"(r2), "=r"(r3) : "r"(addr));
}
__device__ __forceinline__ void mma_k16(float c[4], u32 a0, u32 a1, u32 a2, u32 a3,
                                        u32 b0, u32 b1) {
    asm volatile(
        "mma.sync.aligned.m16n8k16.row.col.f32.f16.f16.f32 "
        "{%0,%1,%2,%3}, {%4,%5,%6,%7}, {%8,%9}, {%0,%1,%2,%3};"
        : "+f"(c[0]), "+f"(c[1]), "+f"(c[2]), "+f"(c[3])
        : "r"(a0), "r"(a1), "r"(a2), "r"(a3), "r"(b0), "r"(b1));
}

// ---- setup: fold weights into fp16 B-matrix, once ----
__global__ void kan_setup(const float* __restrict__ base_w,
                          const float* __restrict__ spline_w,
                          const float* __restrict__ spline_s) {
    int idx = threadIdx.x;
    for (; idx < 9 * 8 * 16; idx += 128) {
        int tap = idx >> 7, rem = idx & 127, n = rem >> 4, k = rem & 15;
        float v = 0.0f;
        if (k == 0 || k == 9) {
            v = base_w[n * 9 + tap];
            g_Bt[idx] = __float2half_rn(v);
        } else if (k <= 8) {
            v = spline_w[(n * 9 + tap) * NCONV + (k - 1)] * spline_s[n * 9 + tap];
            g_Bt[idx] = __float2half_rn(v);
        } else if (k == 10) {
            float bw = base_w[n * 9 + tap];
            g_Bt[idx] = __float2half_rn(bw - __half2float(__float2half_rn(bw)));
        } else {
            g_Bt[idx] = __float2half_rn(0.0f);
        }
    }
}

__global__ __launch_bounds__(128, 8)
void kan_hmma3(const float* __restrict__ x,
               const float* __restrict__ grid_,
               float* __restrict__ out) {
    // feature plane: 4 input rows x 64 cols, PX bytes per pixel
    __shared__ __align__(16) char s_feat[4 * 64 * PX];   // 12288 B

    const int tid  = threadIdx.x;
    const int w    = tid >> 5;
    const int lane = tid & 31;
    const int tile = blockIdx.x;     // 0..30 (output rows 2*tile, 2*tile+1)
    const int img  = blockIdx.y;     // 0..255

    // ---- B fragments straight from global (L1-hot after first block) ----
    u32 bf0[9], bf1[9];
    {
        const __half* bb = g_Bt + (lane >> 2) * 16 + 2 * (lane & 3);
        #pragma unroll
        for (int tap = 0; tap < 9; ++tap) {
            bf0[tap] = *(const u32*)(bb + tap * 128);
            bf1[tap] = *(const u32*)(bb + tap * 128 + 8);
        }
    }

    const float g0    = grid_[0];
    const float inv_h = 1.0f / (grid_[1] - grid_[0]);

    // ---- A-build: 4 input rows x 64 cols, 16-half feature vector per pixel ----
    const float* xin = x + img * 4096 + tile * 2 * 64;
    #pragma unroll
    for (int e = tid; e < 256; e += 128) {
        float v = xin[e];            // rows 2*tile .. 2*tile+3 (tile<=30 -> row<=63)

        float sig  = 1.0f / (1.0f + __expf(-v));
        float silu = v * sig;
        float slo  = silu - __half2float(__float2half_rn(silu));  // fp16 residual

        float u  = (v - g0) * inv_h;
        float fj = floorf(u);
        int   j0 = (int)fj;
        float tt = u - fj;
        float t2 = tt * tt, t3 = t2 * tt, om = 1.0f - tt;
        const float s6 = 1.0f / 6.0f;
        float c0 = om * om * om * s6;
        float c1 = (3.0f * t3 - 6.0f * t2 + 4.0f) * s6;
        float c2 = (-3.0f * t3 + 3.0f * t2 + 3.0f * tt + 1.0f) * s6;
        float c3 = t3 * s6;
        int jb = j0 - 3;             // basis index holding c0

        float bas[8];
        #pragma unroll
        for (int j = 0; j < 8; ++j) {
            int d = j - jb;
            bas[j] = (d == 0) ? c0 : (d == 1) ? c1 : (d == 2) ? c2 : (d == 3) ? c3 : 0.0f;
        }

        char* bp = s_feat + e * PX;
        *(uint4*)bp = make_uint4(pack_h2(silu,   bas[0]),
                                 pack_h2(bas[1], bas[2]),
                                 pack_h2(bas[3], bas[4]),
                                 pack_h2(bas[5], bas[6]));
        *(uint4*)(bp + 16) = make_uint4(pack_h2(bas[7], slo),
                                        pack_h2(silu, 0.0f), 0u, 0u);
    }
    __syncthreads();

    // ---- tensor phase: warp w owns m16-tiles 2w, 2w+1 over 124 pixels ----
    const u32 fb = smem_u32(s_feat);
    float c[2][4];
    u32 abase[2];
    #pragma unroll
    for (int tau = 0; tau < 2; ++tau) {
        int m  = (w * 2 + tau) * 16 + (lane & 15);
        int rt = (m >= WO) ? ((m >= 2 * WO) ? 2 : 1) : 0;
        int xo = m - rt * WO;
        if (m >= 2 * WO) { rt = 0; xo = 0; }    // pad rows -> dummy addr
        abase[tau] = fb + (u32)((rt * 64 + xo) * PX) + (u32)((lane >> 4) * 16);
        #pragma unroll
        for (int i = 0; i < 4; ++i) c[tau][i] = 0.0f;
    }

    #pragma unroll
    for (int tap = 0; tap < 9; ++tap) {
        const int dy = tap / 3, dx = tap % 3;
        const u32 off = (u32)((dy * 64 + dx) * PX);
        #pragma unroll
        for (int tau = 0; tau < 2; ++tau) {
            u32 a0, a1, a2, a3;
            ldsm_x4(a0, a1, a2, a3, abase[tau] + off);
            mma_k16(c[tau], a0, a1, a2, a3, bf0[tap], bf1[tap]);
        }
    }

    // ---- store: c rows = pixel index, c cols = conv index ----
    const int n0 = 2 * (lane & 3);
    #pragma unroll
    for (int tau = 0; tau < 2; ++tau) {
        #pragma unroll
        for (int g = 0; g < 2; ++g) {
            int m = (w * 2 + tau) * 16 + g * 8 + (lane >> 2);
            if (m < 2 * WO) {
                int rt = (m >= WO) ? 1 : 0;
                int xo = m - rt * WO;
                int y  = tile * 2 + rt;
                float* p0 = out + ((img * NCONV + n0) * HO + y) * WO + xo;
                p0[0]       = c[tau][g * 2 + 0];
                p0[HO * WO] = c[tau][g * 2 + 1];
            }
        }
    }
}

extern "C" void kernel_launch(void* const* d_in, const int* in_sizes, int n_in,
                              void* d_out, int out_size) {
    const float* x  = (const float*)d_in[0];
    const float* bw = (const float*)d_in[1];
    const float* sw = (const float*)d_in[2];
    const float* ss = (const float*)d_in[3];
    const float* gr = (const float*)d_in[4];
    float* out = (float*)d_out;

    kan_setup<<<1, 128>>>(bw, sw, ss);
    dim3 grd(31, 256);   // 31 two-row tiles x 256 images
    kan_hmma3<<<grd, 128>>>(x, gr, out);
}

// round 10
// speedup vs baseline: 1.2622x; 1.2622x over previous
#include <cuda_runtime.h>
#include <cstdint>

#define NCONV   8
#define HO      62
#define WO      62
#define NCOEF   8
#define INFEAT  9
#define NFEAT   9
#define BAND_R  4      // output rows per block
#define TROWS   6      // input rows per tile
#define TCOLS   68
#define PLANE   (TROWS * TCOLS)
#define NTHREADS 128

typedef unsigned long long u64;

__device__ __forceinline__ void fma2(u64 &d, u64 a, u64 b) {
    asm("fma.rn.f32x2 %0, %1, %2, %0;" : "+l"(d) : "l"(a), "l"(b));
}
__device__ __forceinline__ u64 dup2(float v) {
    u64 r; asm("mov.b64 %0, {%1, %1};" : "=l"(r) : "f"(v)); return r;
}
__device__ __forceinline__ float lo32(u64 a) { return __uint_as_float((unsigned)(a & 0xFFFFFFFFULL)); }
__device__ __forceinline__ float hi32(u64 a) { return __uint_as_float((unsigned)(a >> 32)); }

__global__ __launch_bounds__(NTHREADS, 10)
void kan_conv_kernel(const float* __restrict__ x,
                     const float* __restrict__ base_w,
                     const float* __restrict__ spline_w,
                     const float* __restrict__ spline_s,
                     const float* __restrict__ grid,
                     float* __restrict__ out) {
    __shared__ __align__(16) float s_feat[NFEAT * PLANE];       // 9*408*4 = 14688 B
    __shared__ __align__(16) float s_w[NFEAT * INFEAT * NCONV]; // 2592 B

    const int tid  = threadIdx.x;
    const int band = blockIdx.x;          // 0..15
    const int img  = blockIdx.y;          // 0..255
    const int y0   = band * BAND_R;

    // ---- Phase 0a: combined weights ----
    for (int idx = tid; idx < NFEAT * INFEAT * NCONV; idx += NTHREADS) {
        int f    = idx / (INFEAT * NCONV);
        int rest = idx % (INFEAT * NCONV);
        int i    = rest / NCONV;
        int n    = rest % NCONV;
        float v;
        if (f == 0) v = base_w[n * INFEAT + i];
        else        v = spline_w[(n * INFEAT + i) * NCOEF + (f - 1)] * spline_s[n * INFEAT + i];
        s_w[idx] = v;
    }

    // ---- Phase 0b: zero-fill the 8 basis planes ----
    {
        float4 z4 = make_float4(0.f, 0.f, 0.f, 0.f);
        float4* zp = (float4*)(s_feat + PLANE);
        #pragma unroll 4
        for (int i = tid; i < (8 * PLANE) / 4; i += NTHREADS)
            zp[i] = z4;
    }

    const float g0    = grid[0];
    const float inv_h = 1.0f / (grid[1] - grid[0]);
    __syncthreads();

    // ---- Phase 1: silu + 4 nonzero cubic B-spline bases ----
    const float* xin = x + img * 4096;
    #pragma unroll
    for (int e = tid; e < TROWS * 64; e += NTHREADS) {
        int row  = e >> 6;
        int col  = e & 63;
        int y_in = y0 + row;
        float v  = (y_in < 64) ? xin[y_in * 64 + col] : 0.0f;

        float* bp = &s_feat[row * TCOLS + col];
        float sig = 1.0f / (1.0f + __expf(-v));
        bp[0] = v * sig;

        float u  = (v - g0) * inv_h;
        float fj = floorf(u);
        int   j0 = (int)fj;
        float t  = u - fj;
        float t2 = t * t, t3 = t2 * t, om = 1.0f - t;
        const float s6 = 1.0f / 6.0f;
        float c0 = om * om * om * s6;
        float c1 = (3.0f * t3 - 6.0f * t2 + 4.0f) * s6;
        float c2 = (-3.0f * t3 + 3.0f * t2 + 3.0f * t + 1.0f) * s6;
        float c3 = t3 * s6;

        int jj;
        jj = j0 - 3; if (jj >= 0 && jj <= 7) bp[(1 + jj) * PLANE] = c0;
        jj = j0 - 2; if (jj >= 0 && jj <= 7) bp[(1 + jj) * PLANE] = c1;
        jj = j0 - 1; if (jj >= 0 && jj <= 7) bp[(1 + jj) * PLANE] = c2;
        jj = j0;     if (jj >= 0 && jj <= 7) bp[(1 + jj) * PLANE] = c3;
    }
    __syncthreads();

    // ---- Phase 2: 3x3 conv over 9 feature planes -> 8 outputs, 2 px/thread ----
    const int cg = tid & 31;          // 0..31
    const int r  = tid >> 5;          // 0..3
    const int x0 = cg * 2;            // 0..62
    const int y  = y0 + r;

    u64 acc[2][4];
    #pragma unroll
    for (int p = 0; p < 2; ++p)
        #pragma unroll
        for (int q = 0; q < 4; ++q) acc[p][q] = 0ULL;

    const float* fbase = &s_feat[r * TCOLS + x0];

    // prefetch first iteration's feature window (4 floats via 2x LDS.64)
    float2 va = *(const float2*)(fbase);
    float2 vb = *(const float2*)(fbase + 2);

    #pragma unroll
    for (int it = 0; it < 27; ++it) {
        const int dy = it / 9, f = it % 9;

        // prefetch next iteration's features before this iteration's FMAs
        float2 na, nb;
        if (it < 26) {
            const int it2 = it + 1;
            const float* np = fbase + ((it2 % 9) * TROWS + (it2 / 9)) * TCOLS;
            na = *(const float2*)(np);
            nb = *(const float2*)(np + 2);
        }

        u64 dv[4];
        dv[0] = dup2(va.x); dv[1] = dup2(va.y);
        dv[2] = dup2(vb.x); dv[3] = dup2(vb.y);

        #pragma unroll
        for (int dx = 0; dx < 3; ++dx) {
            const float* wptr = &s_w[(f * INFEAT + dy * 3 + dx) * NCONV];
            ulonglong2 wa = *(const ulonglong2*)(wptr);
            ulonglong2 wb = *(const ulonglong2*)(wptr + 4);
            #pragma unroll
            for (int p = 0; p < 2; ++p) {
                u64 fd = dv[dx + p];
                fma2(acc[p][0], fd, wa.x);
                fma2(acc[p][1], fd, wa.y);
                fma2(acc[p][2], fd, wb.x);
                fma2(acc[p][3], fd, wb.y);
            }
        }
        va = na; vb = nb;
    }

    // ---- store: out[((img*8 + n)*62 + y)*62 + x], STG.64 pairs ----
    if (x0 < WO - 1 && y < HO) {      // cg==31 (x0=62) fully out of range
        #pragma unroll
        for (int q = 0; q < 4; ++q) {
            float* po_lo = out + ((img * NCONV + 2 * q    ) * HO + y) * WO + x0;
            float* po_hi = out + ((img * NCONV + 2 * q + 1) * HO + y) * WO + x0;
            *(float2*)po_lo = make_float2(lo32(acc[0][q]), lo32(acc[1][q]));
            *(float2*)po_hi = make_float2(hi32(acc[0][q]), hi32(acc[1][q]));
        }
    }
}

extern "C" void kernel_launch(void* const* d_in, const int* in_sizes, int n_in,
                              void* d_out, int out_size) {
    const float* x  = (const float*)d_in[0];
    const float* bw = (const float*)d_in[1];
    const float* sw = (const float*)d_in[2];
    const float* ss = (const float*)d_in[3];
    const float* gr = (const float*)d_in[4];
    float* out = (float*)d_out;

    dim3 grd(16, 256);   // 16 four-row bands x 256 images
    kan_conv_kernel<<<grd, NTHREADS>>>(x, bw, sw, ss, gr, out);
}